// round 7
// baseline (speedup 1.0000x reference)
#include <cuda_runtime.h>
#include <math.h>

// Problem constants
#define BB 16
#define CC 512
#define NN 1024   // H*W
#define GG 32
#define CG 16     // CC/GG
#define TEXT 180
#define FF 1024
#define EPSV 1e-6f
#define SCALE 0.04419417382415922f   // 512^-0.5
#define ROWS 64

// ---- scratch (static device memory) ----
__device__ float d_wosum[CC];
__device__ float d_wgsum[GG];
__device__ float d_c0part[GG];
__device__ float d_bqsum;
__device__ float d_k[BB*FF];
__device__ float d_v[BB*FF];
__device__ float d_psum[BB*GG*4];     // per-quarter stats partials
__device__ float d_psum2[BB*GG*4];
__device__ __align__(16) float d_P[BB*GG*NN];  // 2 MB
__device__ __align__(16) float d_h2[BB*NN];

// ============================================================
// Kernel 1 (fused): gn streaming + prep roles
//   blocks 0..2047    : gn role, block = (bg, quarter). 16ch x 256n.
//   blocks 2048..2111 : k/v projections
//   blocks 2112..2119 : wo row sums
//   block  2120       : bq sum
// ============================================================
__global__ void gn_kernel(const float* __restrict__ x,
                          const float* __restrict__ cond,
                          const float* __restrict__ gamma,
                          const float* __restrict__ beta,
                          const float* __restrict__ wq,
                          const float* __restrict__ bq,
                          const float* __restrict__ wk,
                          const float* __restrict__ bk,
                          const float* __restrict__ wv,
                          const float* __restrict__ bv,
                          const float* __restrict__ wo)
{
    int blk = blockIdx.x;
    int tid = threadIdx.x;

    if (blk < 2048) {
        // ---------------- gn role ----------------
        __shared__ float4 wpart[8][4];
        __shared__ float  colsum_s[16];
        __shared__ float  wgs[16];
        __shared__ float4 sh4[4][64];
        __shared__ float  sw[8], sw2[8];

        int bg = blk >> 2, q = blk & 3;
        int b = bg >> 5, g = bg & 31;
        int c0 = g * CG;
        int hi = tid >> 6, lo = tid & 63;
        int warp = tid >> 5, lane = tid & 31;

        // --- inline wq colsum for this group's 16 columns (float4, L2) ---
        {
            const float4* wq4 = (const float4*)wq;
            int col4 = tid & 3;
            float4 pa = make_float4(0.f, 0.f, 0.f, 0.f);
            #pragma unroll
            for (int j = 0; j < 8; j++) {
                int row = (tid >> 2) + j * 64;
                float4 w = wq4[row * 128 + g * 4 + col4];
                pa.x += w.x; pa.y += w.y; pa.z += w.z; pa.w += w.w;
            }
            #pragma unroll
            for (int off = 4; off < 32; off <<= 1) {
                pa.x += __shfl_xor_sync(0xffffffffu, pa.x, off);
                pa.y += __shfl_xor_sync(0xffffffffu, pa.y, off);
                pa.z += __shfl_xor_sync(0xffffffffu, pa.z, off);
                pa.w += __shfl_xor_sync(0xffffffffu, pa.w, off);
            }
            if (lane < 4) wpart[warp][lane] = pa;
        }
        __syncthreads();
        if (tid < 4) {
            float4 cs = wpart[0][tid];
            #pragma unroll
            for (int w = 1; w < 8; w++) {
                float4 t = wpart[w][tid];
                cs.x += t.x; cs.y += t.y; cs.z += t.z; cs.w += t.w;
            }
            ((float4*)colsum_s)[tid] = cs;
            float4 gm = ((const float4*)gamma)[g * 4 + tid];
            float4 wg;
            wg.x = cs.x * gm.x; wg.y = cs.y * gm.y;
            wg.z = cs.z * gm.z; wg.w = cs.w * gm.w;
            ((float4*)wgs)[tid] = wg;
        }
        __syncthreads();

        // one block per group publishes group constants
        if (bg < 32 && q == 0 && tid == 0) {
            float cs = 0.f, ws = 0.f;
            #pragma unroll
            for (int c = 0; c < CG; c++) {
                cs += colsum_s[c] * beta[c0 + c];
                ws += wgs[c];
            }
            d_c0part[g] = cs;
            d_wgsum[g]  = ws;
        }

        // --- main stream: 4 independent float4 loads (4 channels, same n) ---
        const float4* x4 = (const float4*)x + (size_t)(b * CC + c0) * 256 + q * 64;

        float4 xv[4];
        #pragma unroll
        for (int j = 0; j < 4; j++)
            xv[j] = x4[(hi + 4 * j) * 256 + lo];

        float4 pn = make_float4(0.f, 0.f, 0.f, 0.f);
        float s = 0.f, s2 = 0.f;
        #pragma unroll
        for (int j = 0; j < 4; j++) {
            float w = wgs[hi + 4 * j];
            float4 v = xv[j];
            pn.x = fmaf(w, v.x, pn.x);
            pn.y = fmaf(w, v.y, pn.y);
            pn.z = fmaf(w, v.z, pn.z);
            pn.w = fmaf(w, v.w, pn.w);
            s  += v.x + v.y + v.z + v.w;
            s2 += v.x*v.x + v.y*v.y + v.z*v.z + v.w*v.w;
        }

        sh4[hi][lo] = pn;

        #pragma unroll
        for (int off = 16; off > 0; off >>= 1) {
            s  += __shfl_xor_sync(0xffffffffu, s,  off);
            s2 += __shfl_xor_sync(0xffffffffu, s2, off);
        }
        if (lane == 0) { sw[warp] = s; sw2[warp] = s2; }
        __syncthreads();

        if (tid < 64) {
            float4 a = sh4[0][tid], b1 = sh4[1][tid], c1 = sh4[2][tid], d1 = sh4[3][tid];
            float4 r;
            r.x = a.x + b1.x + c1.x + d1.x;
            r.y = a.y + b1.y + c1.y + d1.y;
            r.z = a.z + b1.z + c1.z + d1.z;
            r.w = a.w + b1.w + c1.w + d1.w;
            ((float4*)d_P)[bg * 256 + q * 64 + tid] = r;
        }
        if (tid == 0) {
            float ts = 0.f, ts2 = 0.f;
            #pragma unroll
            for (int i = 0; i < 8; i++) { ts += sw[i]; ts2 += sw2[i]; }
            d_psum[blk]  = ts;
            d_psum2[blk] = ts2;
        }
    } else if (blk < 2048 + 64) {
        // ---------------- k/v projection role ----------------
        __shared__ float cs[TEXT];
        int blk2 = blk - 2048;
        int b = blk2 >> 2;
        int f = ((blk2 & 3) << 8) + tid;
        if (tid < TEXT) cs[tid] = cond[b * TEXT + tid];
        __syncthreads();
        float ak = bk[f], av = bv[f];
        const float4* wkr = (const float4*)(wk + (size_t)f * TEXT);
        const float4* wvr = (const float4*)(wv + (size_t)f * TEXT);
        const float4* cs4 = (const float4*)cs;
        #pragma unroll 5
        for (int t = 0; t < TEXT / 4; t++) {
            float4 c  = cs4[t];
            float4 k4 = wkr[t];
            float4 v4 = wvr[t];
            ak = fmaf(c.x, k4.x, ak); ak = fmaf(c.y, k4.y, ak);
            ak = fmaf(c.z, k4.z, ak); ak = fmaf(c.w, k4.w, ak);
            av = fmaf(c.x, v4.x, av); av = fmaf(c.y, v4.y, av);
            av = fmaf(c.z, v4.z, av); av = fmaf(c.w, v4.w, av);
        }
        d_k[b * FF + f] = ak;
        d_v[b * FF + f] = av;
    } else if (blk < 2048 + 64 + 8) {
        // ---------------- wo row sums ----------------
        int blk3 = blk - (2048 + 64);
        int warp = tid >> 5, lane = tid & 31;
        int o = blk3 * 64 + warp * 8;
        #pragma unroll
        for (int j = 0; j < 8; j++) {
            const float4* wr = (const float4*)(wo + (size_t)(o + j) * CC);
            float s = 0.f;
            #pragma unroll
            for (int c = 0; c < 4; c++) {
                float4 v = wr[lane + c * 32];
                s += v.x + v.y + v.z + v.w;
            }
            #pragma unroll
            for (int off = 16; off > 0; off >>= 1)
                s += __shfl_down_sync(0xffffffffu, s, off);
            if (lane == 0) d_wosum[o + j] = s;
        }
    } else {
        if (tid < 32) {
            float s = 0.f;
            #pragma unroll
            for (int i = 0; i < CC / 32; i++) s += bq[tid + i * 32];
            #pragma unroll
            for (int off = 16; off > 0; off >>= 1)
                s += __shfl_down_sync(0xffffffffu, s, off);
            if (tid == 0) d_bqsum = s;
        }
    }
}

// ============================================================
// Kernel 2: softmax mixture -> h2[b,n]
// grid 256, one warp per n-row
// ============================================================
__global__ void attn_kernel()
{
    int blk = blockIdx.x;
    int b  = blk >> 4;
    int n0 = (blk & 15) * ROWS;
    int tid = threadIdx.x;
    int warp = tid >> 5, lane = tid & 31;

    __shared__ float ks[FF], vs[FF];
    __shared__ float Ps[GG][ROWS + 1];
    __shared__ float Ss[ROWS];
    __shared__ float rstd_s[GG];
    __shared__ float red[20];

    for (int i = tid; i < FF; i += 256) {
        ks[i] = d_k[b * FF + i];
        vs[i] = d_v[b * FF + i];
    }
    for (int i = tid; i < GG * ROWS; i += 256) {
        int g = i >> 6, nn = i & (ROWS - 1);
        Ps[g][nn] = d_P[(size_t)(b * GG + g) * NN + n0 + nn];
    }
    // finalize group stats from per-quarter partials
    float mu_l = 0.f;
    if (tid < GG) {
        int base = (b * GG + tid) * 4;
        float ps  = (d_psum [base] + d_psum [base + 1])
                  + (d_psum [base + 2] + d_psum [base + 3]);
        float ps2 = (d_psum2[base] + d_psum2[base + 1])
                  + (d_psum2[base + 2] + d_psum2[base + 3]);
        float mean = ps * (1.f / 16384.f);
        float var  = ps2 * (1.f / 16384.f) - mean * mean;
        rstd_s[tid] = rsqrtf(var + EPSV);
        mu_l = mean;
    }
    __syncthreads();

    // per-b kmax/kmin + T[b]
    float km = -1e30f, kn = 1e30f;
    for (int i = tid; i < FF; i += 256) {
        float kk = ks[i];
        km = fmaxf(km, kk);
        kn = fminf(kn, kk);
    }
    #pragma unroll
    for (int off = 16; off > 0; off >>= 1) {
        km = fmaxf(km, __shfl_xor_sync(0xffffffffu, km, off));
        kn = fminf(kn, __shfl_xor_sync(0xffffffffu, kn, off));
    }
    if (lane == 0) { red[warp] = km; red[8 + warp] = kn; }
    float Tp = 0.f;
    if (tid < GG)
        Tp = -mu_l * rstd_s[tid] * d_wgsum[tid] + d_c0part[tid];
    if (warp == 0) {
        #pragma unroll
        for (int off = 16; off > 0; off >>= 1)
            Tp += __shfl_xor_sync(0xffffffffu, Tp, off);
        if (lane == 0) red[16] = Tp + d_bqsum;
    }
    __syncthreads();

    float kmax = red[0], kmin = red[8];
    #pragma unroll
    for (int i = 1; i < 8; i++) {
        kmax = fmaxf(kmax, red[i]);
        kmin = fminf(kmin, red[8 + i]);
    }
    float Tc = red[16];

    if (tid < ROWS) {
        float s = Tc;
        #pragma unroll
        for (int g = 0; g < GG; g++) s = fmaf(rstd_s[g], Ps[g][tid], s);
        Ss[tid] = SCALE * s;
    }
    __syncthreads();

    for (int r = warp; r < ROWS; r += 8) {
        float a = Ss[r];
        float shift = (a >= 0.f) ? a * kmax : a * kmin;
        float num = 0.f, den = 0.f;
        #pragma unroll
        for (int f = lane; f < FF; f += 32) {
            float e = __expf(fmaf(a, ks[f], -shift));
            den += e;
            num = fmaf(vs[f], e, num);
        }
        #pragma unroll
        for (int off = 16; off > 0; off >>= 1) {
            num += __shfl_xor_sync(0xffffffffu, num, off);
            den += __shfl_xor_sync(0xffffffffu, den, off);
        }
        if (lane == 0) d_h2[b * NN + n0 + r] = num / den;
    }
}

// ============================================================
// Kernel 3: y = x + h2[b,n]*wosum[o] + bo[o]  — ILP=2, grid 4096
// ============================================================
__global__ void out_kernel(const float* __restrict__ x,
                           const float* __restrict__ bo,
                           float* __restrict__ y)
{
    int blk = blockIdx.x;
    int tid = threadIdx.x;
    int b  = blk >> 8;            // 256 blocks per batch
    int o0 = (blk & 255) << 1;    // 2 consecutive o rows

    float4 h2 = ((const float4*)d_h2)[b * 256 + tid];

    size_t base = (size_t)(b * CC + o0) * 256 + tid;
    const float4* xr = (const float4*)x + base;
    float4*       yr = (float4*)y + base;

    float4 xv0 = xr[0];
    float4 xv1 = xr[256];

    float ws0 = d_wosum[o0],     bb0 = bo[o0];
    float ws1 = d_wosum[o0 + 1], bb1 = bo[o0 + 1];

    float4 r0, r1;
    r0.x = fmaf(h2.x, ws0, xv0.x + bb0);
    r0.y = fmaf(h2.y, ws0, xv0.y + bb0);
    r0.z = fmaf(h2.z, ws0, xv0.z + bb0);
    r0.w = fmaf(h2.w, ws0, xv0.w + bb0);
    r1.x = fmaf(h2.x, ws1, xv1.x + bb1);
    r1.y = fmaf(h2.y, ws1, xv1.y + bb1);
    r1.z = fmaf(h2.z, ws1, xv1.z + bb1);
    r1.w = fmaf(h2.w, ws1, xv1.w + bb1);

    __stcs(yr, r0);          // streaming store: evict-first, keep x in L2
    __stcs(yr + 256, r1);
}

// ============================================================
extern "C" void kernel_launch(void* const* d_in, const int* in_sizes, int n_in,
                              void* d_out, int out_size)
{
    const float* x     = (const float*)d_in[0];
    const float* cond  = (const float*)d_in[1];
    const float* gamma = (const float*)d_in[2];
    const float* beta  = (const float*)d_in[3];
    const float* wq    = (const float*)d_in[4];
    const float* bq    = (const float*)d_in[5];
    const float* wk    = (const float*)d_in[6];
    const float* bk    = (const float*)d_in[7];
    const float* wv    = (const float*)d_in[8];
    const float* bv    = (const float*)d_in[9];
    const float* wo    = (const float*)d_in[10];
    const float* bo    = (const float*)d_in[11];
    float* y = (float*)d_out;

    gn_kernel<<<2048 + 64 + 8 + 1, 256>>>(x, cond, gamma, beta, wq, bq,
                                          wk, bk, wv, bv, wo);
    attn_kernel<<<BB * (NN / ROWS), 256>>>();
    out_kernel<<<(BB * CC) / 2, 256>>>(x, bo, y);
}